// round 10
// baseline (speedup 1.0000x reference)
#include <cuda_runtime.h>
#include <math.h>
#include <stdint.h>

// Problem constants
#define B_   16
#define C_   512
#define NH_  8
#define HD_  64
#define N_   1024
#define QSCALE 0.125f

typedef unsigned long long ull;

// ---------------------------------------------------------------------------
// Scratch (device globals) — pure fp32 pipeline.
// ---------------------------------------------------------------------------
__device__ float g_qkv[(size_t)3 * B_ * C_ * N_];   // [s][b][c][n] (Q pre-scaled)
__device__ float g_attn[(size_t)B_ * C_ * N_];      // [b][c][n]

// ---------------------------------------------------------------------------
// Packed f32x2 helpers (sm_100+ family PTX)
// ---------------------------------------------------------------------------
__device__ __forceinline__ ull pk2(float x, float y) {
    ull r;
    asm("mov.b64 %0, {%1, %2};"
        : "=l"(r) : "r"(__float_as_uint(x)), "r"(__float_as_uint(y)));
    return r;
}
__device__ __forceinline__ void up2(ull v, float& x, float& y) {
    uint32_t a, b;
    asm("mov.b64 {%0, %1}, %2;" : "=r"(a), "=r"(b) : "l"(v));
    x = __uint_as_float(a); y = __uint_as_float(b);
}
__device__ __forceinline__ ull fma2(ull a, ull b, ull c) {
    ull d;
    asm("fma.rn.f32x2 %0, %1, %2, %3;" : "=l"(d) : "l"(a), "l"(b), "l"(c));
    return d;
}
__device__ __forceinline__ ull mul2(ull a, ull b) {
    ull d;
    asm("mul.rn.f32x2 %0, %1, %2;" : "=l"(d) : "l"(a), "l"(b));
    return d;
}

// ---------------------------------------------------------------------------
// f32x2 GEMM v2: D[o][n] = sum_c W[o][c] * X[b][c][n].
// Block 128(o) x 128(n), BK=16, 256 threads (16x16), 8x8 micro-tile.
// v2: A read as LDS.128 pairs (6 LDS / 32 fma2 per k-step) + 2-stage global
// prefetch into registers.
// MODE 0: scatter fp32 into g_qkv (Q rows scaled).  MODE 1: +bias -> out.
// ---------------------------------------------------------------------------
template<int MODE>
__global__ __launch_bounds__(256)
void gemm_f32x2(const float* __restrict__ W, const float* __restrict__ Xin,
                const float* __restrict__ bias, float* __restrict__ out)
{
    __shared__ ull   As2[16][128];   // [k][o], entry = (a, a)    (16 KB)
    __shared__ float Bs[16][128];    // [k][n]                     (8 KB)

    const int b  = blockIdx.z;
    const int o0 = blockIdx.x * 128;
    const int n0 = blockIdx.y * 128;
    const int tid = threadIdx.x;
    const int tx = tid & 15, ty = tid >> 4;

    const float* Xb = (MODE == 1 ? g_attn : Xin) + (size_t)b * C_ * N_;

    // per-thread gmem slots (2 A + 2 B float4 per k-tile)
    const int am[2] = { (tid + 0)   >> 2, (tid + 256) >> 2 };
    const int aq[2] = { (tid + 0)   & 3,  (tid + 256) & 3 };
    const int bk[2] = { (tid + 0)   >> 5, (tid + 256) >> 5 };
    const int bj[2] = { (tid + 0)   & 31, (tid + 256) & 31 };

    ull acc[8][4];
    #pragma unroll
    for (int i = 0; i < 8; i++)
        #pragma unroll
        for (int j = 0; j < 4; j++) acc[i][j] = 0ull;

    // prologue prefetch (kt = 0)
    float4 pa[2], pb[2];
    #pragma unroll
    for (int r = 0; r < 2; r++) {
        pa[r] = *(const float4*)&W[(size_t)(o0 + am[r]) * C_ + aq[r] * 4];
        pb[r] = *(const float4*)&Xb[(size_t)bk[r] * N_ + n0 + bj[r] * 4];
    }

    for (int kt = 0; kt < C_; kt += 16) {
        // store prefetched tile to smem
        #pragma unroll
        for (int r = 0; r < 2; r++) {
            As2[aq[r] * 4 + 0][am[r]] = pk2(pa[r].x, pa[r].x);
            As2[aq[r] * 4 + 1][am[r]] = pk2(pa[r].y, pa[r].y);
            As2[aq[r] * 4 + 2][am[r]] = pk2(pa[r].z, pa[r].z);
            As2[aq[r] * 4 + 3][am[r]] = pk2(pa[r].w, pa[r].w);
            *(float4*)&Bs[bk[r]][bj[r] * 4] = pb[r];
        }
        __syncthreads();

        // prefetch next tile (overlaps compute)
        if (kt + 16 < C_) {
            #pragma unroll
            for (int r = 0; r < 2; r++) {
                pa[r] = *(const float4*)&W[(size_t)(o0 + am[r]) * C_ + kt + 16 + aq[r] * 4];
                pb[r] = *(const float4*)&Xb[(size_t)(kt + 16 + bk[r]) * N_ + n0 + bj[r] * 4];
            }
        }

        #pragma unroll
        for (int k = 0; k < 16; k++) {
            // A: 4 x LDS.128 (broadcast), B: 2 x LDS.128
            ulonglong2 a01 = *(const ulonglong2*)&As2[k][ty * 8 + 0];
            ulonglong2 a23 = *(const ulonglong2*)&As2[k][ty * 8 + 2];
            ulonglong2 a45 = *(const ulonglong2*)&As2[k][ty * 8 + 4];
            ulonglong2 a67 = *(const ulonglong2*)&As2[k][ty * 8 + 6];
            ull aa[8] = { a01.x, a01.y, a23.x, a23.y, a45.x, a45.y, a67.x, a67.y };
            ulonglong2 b20 = *(const ulonglong2*)&Bs[k][tx * 8];
            ulonglong2 b21 = *(const ulonglong2*)&Bs[k][tx * 8 + 4];
            ull b2[4] = { b20.x, b20.y, b21.x, b21.y };
            #pragma unroll
            for (int i = 0; i < 8; i++)
                #pragma unroll
                for (int j = 0; j < 4; j++)
                    acc[i][j] = fma2(aa[i], b2[j], acc[i][j]);
        }
        __syncthreads();
    }

    #pragma unroll
    for (int i = 0; i < 8; i++) {
        int o = o0 + ty * 8 + i;
        float scale = 1.f, bv = 0.f;
        float* dst;
        if (MODE == 0) {
            int s = o >> 9, rem = o & 511;
            if (s == 0) scale = QSCALE;
            dst = g_qkv + (((size_t)s * B_ + b) * C_ + rem) * N_ + n0;
        } else {
            bv = bias[o];
            dst = out + ((size_t)b * C_ + o) * N_ + n0;
        }
        #pragma unroll
        for (int j = 0; j < 4; j++) {
            float x, y;
            up2(acc[i][j], x, y);
            float2 v;
            if (MODE == 0) { v.x = x * scale; v.y = y * scale; }
            else           { v.x = x + bv;    v.y = y + bv; }
            *(float2*)(dst + tx * 8 + j * 2) = v;
        }
    }
}

// ---------------------------------------------------------------------------
// f32x2 flash attention v2: 1 thread = 1 query.
// Inner loops restructured dq-outer / 4-keys-inner: batched LDS.128 +
// 8 independent fma2 chains (scores) / 2x4 chains (PV).
// ---------------------------------------------------------------------------
__global__ __launch_bounds__(128)
void attn_f32x2()
{
    __shared__ float Ks[64][68];
    __shared__ float Vs[64][68];

    const int bh = blockIdx.x;
    const int b  = bh >> 3, h = bh & 7;
    const int tid = threadIdx.x;
    const int n  = blockIdx.y * 128 + tid;

    const size_t headoff = ((size_t)b * C_ + h * HD_) * N_;
    const float* Qg = g_qkv + headoff;                               // pre-scaled
    const float* Kg = g_qkv + (size_t)1 * B_ * C_ * N_ + headoff;
    const float* Vg = g_qkv + (size_t)2 * B_ * C_ * N_ + headoff;

    ull q2[32], o2[32];
    #pragma unroll
    for (int dp = 0; dp < 32; dp++) {
        q2[dp] = pk2(Qg[(size_t)(2 * dp) * N_ + n], Qg[(size_t)(2 * dp + 1) * N_ + n]);
        o2[dp] = 0ull;
    }
    float m = -INFINITY, l = 0.f;

    for (int t0 = 0; t0 < N_; t0 += 64) {
        // transposed tile loads: gmem [d][n] -> smem [j][d]
        #pragma unroll
        for (int it = 0; it < 8; it++) {
            int f = it * 128 + tid;        // 0..1023
            int d = f >> 4, j4 = f & 15;
            float4 kk = *(const float4*)&Kg[(size_t)d * N_ + t0 + j4 * 4];
            Ks[j4 * 4 + 0][d] = kk.x; Ks[j4 * 4 + 1][d] = kk.y;
            Ks[j4 * 4 + 2][d] = kk.z; Ks[j4 * 4 + 3][d] = kk.w;
            float4 vv = *(const float4*)&Vg[(size_t)d * N_ + t0 + j4 * 4];
            Vs[j4 * 4 + 0][d] = vv.x; Vs[j4 * 4 + 1][d] = vv.y;
            Vs[j4 * 4 + 2][d] = vv.z; Vs[j4 * 4 + 3][d] = vv.w;
        }
        __syncthreads();

        for (int j4 = 0; j4 < 16; j4++) {
            const ulonglong2* kp0 = (const ulonglong2*)&Ks[j4 * 4 + 0][0];
            const ulonglong2* kp1 = (const ulonglong2*)&Ks[j4 * 4 + 1][0];
            const ulonglong2* kp2 = (const ulonglong2*)&Ks[j4 * 4 + 2][0];
            const ulonglong2* kp3 = (const ulonglong2*)&Ks[j4 * 4 + 3][0];

            // scores: 8 independent chains, loads batched 4 per dq
            ull sa0 = 0, sb0 = 0, sa1 = 0, sb1 = 0;
            ull sa2 = 0, sb2 = 0, sa3 = 0, sb3 = 0;
            #pragma unroll
            for (int dq = 0; dq < 16; dq++) {
                ulonglong2 k0 = kp0[dq], k1 = kp1[dq];
                ulonglong2 k2 = kp2[dq], k3 = kp3[dq];
                ull qa = q2[2 * dq], qb = q2[2 * dq + 1];
                sa0 = fma2(qa, k0.x, sa0); sb0 = fma2(qb, k0.y, sb0);
                sa1 = fma2(qa, k1.x, sa1); sb1 = fma2(qb, k1.y, sb1);
                sa2 = fma2(qa, k2.x, sa2); sb2 = fma2(qb, k2.y, sb2);
                sa3 = fma2(qa, k3.x, sa3); sb3 = fma2(qb, k3.y, sb3);
            }
            float s[4];
            {
                float ax, ay, bx, by;
                up2(sa0, ax, ay); up2(sb0, bx, by); s[0] = (ax + bx) + (ay + by);
                up2(sa1, ax, ay); up2(sb1, bx, by); s[1] = (ax + bx) + (ay + by);
                up2(sa2, ax, ay); up2(sb2, bx, by); s[2] = (ax + bx) + (ay + by);
                up2(sa3, ax, ay); up2(sb3, bx, by); s[3] = (ax + bx) + (ay + by);
            }

            // online softmax (lazy rescale)
            float gm = fmaxf(fmaxf(s[0], s[1]), fmaxf(s[2], s[3]));
            if (gm > m) {
                float corr = __expf(m - gm);        // exp(-inf)=0 first tile
                l *= corr;
                ull cc = pk2(corr, corr);
                #pragma unroll
                for (int dp = 0; dp < 32; dp++) o2[dp] = mul2(o2[dp], cc);
                m = gm;
            }
            float p0 = __expf(s[0] - m), p1 = __expf(s[1] - m);
            float p2 = __expf(s[2] - m), p3 = __expf(s[3] - m);
            l += (p0 + p1) + (p2 + p3);
            ull pp0 = pk2(p0, p0), pp1 = pk2(p1, p1);
            ull pp2 = pk2(p2, p2), pp3 = pk2(p3, p3);

            const ulonglong2* vp0 = (const ulonglong2*)&Vs[j4 * 4 + 0][0];
            const ulonglong2* vp1 = (const ulonglong2*)&Vs[j4 * 4 + 1][0];
            const ulonglong2* vp2 = (const ulonglong2*)&Vs[j4 * 4 + 2][0];
            const ulonglong2* vp3 = (const ulonglong2*)&Vs[j4 * 4 + 3][0];

            // PV: per dq, 4 batched loads then 2 chains of 4 fma2
            #pragma unroll
            for (int dq = 0; dq < 16; dq++) {
                ulonglong2 v0 = vp0[dq], v1 = vp1[dq];
                ulonglong2 v2 = vp2[dq], v3 = vp3[dq];
                ull oA = o2[2 * dq], oB = o2[2 * dq + 1];
                oA = fma2(pp0, v0.x, oA); oB = fma2(pp0, v0.y, oB);
                oA = fma2(pp1, v1.x, oA); oB = fma2(pp1, v1.y, oB);
                oA = fma2(pp2, v2.x, oA); oB = fma2(pp2, v2.y, oB);
                oA = fma2(pp3, v3.x, oA); oB = fma2(pp3, v3.y, oB);
                o2[2 * dq] = oA; o2[2 * dq + 1] = oB;
            }
        }
        __syncthreads();
    }

    const float inv = 1.f / l;
    float* Og = g_attn + headoff;
    #pragma unroll
    for (int dp = 0; dp < 32; dp++) {
        float x, y;
        up2(o2[dp], x, y);
        Og[(size_t)(2 * dp) * N_ + n]     = x * inv;   // coalesced per d
        Og[(size_t)(2 * dp + 1) * N_ + n] = y * inv;
    }
}

// ---------------------------------------------------------------------------
extern "C" void kernel_launch(void* const* d_in, const int* in_sizes, int n_in,
                              void* d_out, int out_size)
{
    const float* x      = (const float*)d_in[0];   // [B, C, H, W]
    const float* w_qkv  = (const float*)d_in[1];   // [3C, C]
    const float* w_proj = (const float*)d_in[2];   // [C, C]
    const float* b_proj = (const float*)d_in[3];   // [C]
    float* out = (float*)d_out;

    // 1) QKV GEMM (f32x2) -> g_qkv, Q scaled
    gemm_f32x2<0><<<dim3(3 * C_ / 128, N_ / 128, B_), 256>>>(w_qkv, x, nullptr, nullptr);

    // 2) flash attention (f32x2) -> g_attn
    attn_f32x2<<<dim3(B_ * NH_, N_ / 128), 128>>>();

    // 3) proj GEMM (f32x2) + bias -> out
    gemm_f32x2<1><<<dim3(C_ / 128, N_ / 128, B_), 256>>>(w_proj, nullptr, b_proj, out);
}